// round 15
// baseline (speedup 1.0000x reference)
#include <cuda_runtime.h>
#include <cuda_bf16.h>
#include <cuda_fp16.h>
#include <cstdint>

// Fixed shapes: B=2, H=8, N=256, D=64.  One CTA (256 thr, 8 warps) per query.
// Warp-specialized: warps 0-3 = GEMM1 producers (k-slab of 64 rows each),
// warps 4-7 = softmax+GEMM2 consumers (same k-slab as partner). S passes
// through SMEM fp32 in [64k x 32j] chunks, double-buffered per pair, with
// pair-local named-barrier rendezvous.  All operands staged once up front.
#define NQ 256
#define DD 64
#define NPANEL 4

#define SWZ(x) ((x) ^ (((x) >> 3) & 0x70))

static constexpr uint32_t OFF_K2QH = 0;        // [256 k][64 d] bf16 hi (32 KB)
static constexpr uint32_t OFF_K2QL = 32768;    // lo
static constexpr uint32_t OFF_K1H  = 65536;    // [256 j][64 d] bf16 hi (32 KB)
static constexpr uint32_t OFF_K1L  = 98304;    // lo
static constexpr uint32_t OFF_V1H  = 131072;   // [256 j][64 d] fp16 (32 KB)
static constexpr uint32_t OFF_S    = 163840;   // 4 pairs x 2 bufs x 8 KB fp32 S chunks
static constexpr uint32_t OFF_SRED = 229376;   // [4 pairs][64 d] fp32 (1 KB)
static constexpr uint32_t OFF_SLP  = 230400;   // [4] fp32 lsum
static constexpr uint32_t OFF_SM   = 230416;   // [4] fp32 per-pair max
static constexpr uint32_t SMEM_BYTES = 230432; // <= 232448

// ---------------- PTX helpers ----------------------------------------------
__device__ __forceinline__ uint32_t smem_u32(const void* p) {
    uint32_t a;
    asm("{ .reg .u64 t; cvta.to.shared.u64 t, %1; cvt.u32.u64 %0, t; }" : "=r"(a) : "l"(p));
    return a;
}
__device__ __forceinline__ float ex2f(float x) {
    float y; asm("ex2.approx.ftz.f32 %0, %1;" : "=f"(y) : "f"(x)); return y;
}
__device__ __forceinline__ void named_bar(int id) {
    asm volatile("bar.sync %0, 64;" :: "r"(id) : "memory");
}
__device__ __forceinline__ void ldsm_x4(uint32_t* r, uint32_t addr) {
    asm volatile("ldmatrix.sync.aligned.m8n8.x4.shared.b16 {%0,%1,%2,%3}, [%4];"
                 : "=r"(r[0]), "=r"(r[1]), "=r"(r[2]), "=r"(r[3]) : "r"(addr));
}
__device__ __forceinline__ void ldsm_x4_t(uint32_t* r, uint32_t addr) {
    asm volatile("ldmatrix.sync.aligned.m8n8.x4.trans.shared.b16 {%0,%1,%2,%3}, [%4];"
                 : "=r"(r[0]), "=r"(r[1]), "=r"(r[2]), "=r"(r[3]) : "r"(addr));
}
__device__ __forceinline__ void mma_bf(float* c, const uint32_t* a, uint32_t b0, uint32_t b1) {
    asm("mma.sync.aligned.m16n8k16.row.col.f32.bf16.bf16.f32 "
        "{%0,%1,%2,%3}, {%4,%5,%6,%7}, {%8,%9}, {%0,%1,%2,%3};"
        : "+f"(c[0]), "+f"(c[1]), "+f"(c[2]), "+f"(c[3])
        : "r"(a[0]), "r"(a[1]), "r"(a[2]), "r"(a[3]), "r"(b0), "r"(b1));
}
__device__ __forceinline__ void mma_hf(float* c, const uint32_t* a, uint32_t b0, uint32_t b1) {
    asm("mma.sync.aligned.m16n8k16.row.col.f32.f16.f16.f32 "
        "{%0,%1,%2,%3}, {%4,%5,%6,%7}, {%8,%9}, {%0,%1,%2,%3};"
        : "+f"(c[0]), "+f"(c[1]), "+f"(c[2]), "+f"(c[3])
        : "r"(a[0]), "r"(a[1]), "r"(a[2]), "r"(a[3]), "r"(b0), "r"(b1));
}
__device__ __forceinline__ void split2(float x, float y, uint32_t& h, uint32_t& l) {
    __nv_bfloat162 h2 = __floats2bfloat162_rn(x, y);
    __nv_bfloat162 l2 = __floats2bfloat162_rn(x - __low2float(h2), y - __high2float(h2));
    h = *(uint32_t*)&h2; l = *(uint32_t*)&l2;
}
__device__ __forceinline__ uint32_t packh2_sat(float x, float y) {   // x -> low half
    uint32_t r;
    asm("cvt.rn.satfinite.f16x2.f32 %0, %1, %2;" : "=r"(r) : "f"(y), "f"(x));
    return r;
}

// ---------------- Kernel ----------------------------------------------------
__global__ __launch_bounds__(256, 1)
void trisimp_ws_kernel(const float* __restrict__ q,  const float* __restrict__ k1,
                       const float* __restrict__ v1, const float* __restrict__ k2,
                       const float* __restrict__ v2, float* __restrict__ out)
{
    extern __shared__ char smem[];
    const uint32_t sb = smem_u32(smem);
    const int tid = threadIdx.x, w = tid >> 5, lid = tid & 31;
    const int g = lid >> 2, t = lid & 3;

    const int bhq = blockIdx.x, qi = bhq & 255, bh = bhq >> 8;
    const size_t base = (size_t)bh * NQ * DD;
    const float* Qrow = q  + base + (size_t)qi * DD;
    const float* K1g  = k1 + base;
    const float* V1g  = v1 + base;
    const float* K2g  = k2 + base;
    const float* V2g  = v2 + base;

    const int dp = tid & 31;
    const float2 qme = ((const float2*)Qrow)[dp];
    const float qx = qme.x * 1.4426950408889634f;
    const float qy = qme.y * 1.4426950408889634f;

    // ---- stage everything once: K2q hi/lo, K1 hi/lo, V1 fp16 (all warps) ----
    {
        const float2* K2g2 = (const float2*)K2g;
        const float2* K1g2 = (const float2*)K1g;
        const float2* V1g2 = (const float2*)V1g;
        for (int e2 = tid; e2 < NQ * 32; e2 += 256) {
            const int r = e2 >> 5;
            const uint32_t off = SWZ((uint32_t)r * 128 + (uint32_t)dp * 4);
            {
                const float2 x = K2g2[e2];
                uint32_t h, l; split2(qx * x.x, qy * x.y, h, l);
                *(uint32_t*)(smem + OFF_K2QH + off) = h;
                *(uint32_t*)(smem + OFF_K2QL + off) = l;
            }
            {
                const float2 x = K1g2[e2];
                uint32_t h, l; split2(x.x, x.y, h, l);
                *(uint32_t*)(smem + OFF_K1H + off) = h;
                *(uint32_t*)(smem + OFF_K1L + off) = l;
            }
            {
                const float2 x = V1g2[e2];
                const __half2 hh = __floats2half2_rn(x.x, x.y);
                *(uint32_t*)(smem + OFF_V1H + off) = *(const uint32_t*)&hh;
            }
        }
    }
    __syncthreads();

    const uint32_t lmA_r = (uint32_t)(lid & 15), lmA_c = (uint32_t)(lid >> 4) * 16;
    const uint32_t lmB_r = (uint32_t)((lid >> 4) * 8 + (lid & 7)), lmB_c = (uint32_t)((lid >> 3) & 1) * 16;

    float* sRed = (float*)(smem + OFF_SRED);
    float* sLp  = (float*)(smem + OFF_SLP);
    float* sM   = (float*)(smem + OFF_SM);

    if (w < 4) {
        // ================= PRODUCER: GEMM1 only, k-slab [64w, 64w+64) ========
        const int pair = w;
        const uint32_t sS = OFF_S + (uint32_t)pair * 16384;
        int buf = 0;
        #pragma unroll 1
        for (int ch = 0; ch < 8; ++ch) {           // (panel p, half hh)
            const int p = ch >> 1, hh2 = ch & 1;
            float s[4][4][4];
            #pragma unroll
            for (int mt = 0; mt < 4; ++mt)
                #pragma unroll
                for (int nt = 0; nt < 4; ++nt)
                    #pragma unroll
                    for (int r = 0; r < 4; ++r) s[mt][nt][r] = 0.f;

            #pragma unroll
            for (int kc = 0; kc < 4; ++kc) {
                uint32_t aH[4][4], aL[4][4];
                #pragma unroll
                for (int mt = 0; mt < 4; ++mt) {
                    const uint32_t rb = (uint32_t)(64 * pair + 16 * mt + lmA_r) * 128
                                      + (uint32_t)kc * 32 + lmA_c;
                    ldsm_x4(aH[mt], sb + OFF_K2QH + SWZ(rb));
                    ldsm_x4(aL[mt], sb + OFF_K2QL + SWZ(rb));
                }
                #pragma unroll
                for (int cp = 0; cp < 2; ++cp) {
                    uint32_t bH[4], bL[4];
                    const uint32_t rb = (uint32_t)(64 * p + 32 * hh2 + 16 * cp + lmB_r) * 128
                                      + (uint32_t)kc * 32 + lmB_c;
                    ldsm_x4(bH, sb + OFF_K1H + SWZ(rb));
                    ldsm_x4(bL, sb + OFF_K1L + SWZ(rb));
                    #pragma unroll
                    for (int h = 0; h < 2; ++h)
                        #pragma unroll
                        for (int mt = 0; mt < 4; ++mt)
                            mma_bf(s[mt][2*cp+h], aH[mt], bH[2*h], bH[2*h+1]);
                    #pragma unroll
                    for (int h = 0; h < 2; ++h)
                        #pragma unroll
                        for (int mt = 0; mt < 4; ++mt)
                            mma_bf(s[mt][2*cp+h], aH[mt], bL[2*h], bL[2*h+1]);
                    #pragma unroll
                    for (int h = 0; h < 2; ++h)
                        #pragma unroll
                        for (int mt = 0; mt < 4; ++mt)
                            mma_bf(s[mt][2*cp+h], aL[mt], bH[2*h], bH[2*h+1]);
                }
            }
            // store S chunk [64k x 32j] fp32, swizzled 128B rows
            {
                const uint32_t bb = sS + (uint32_t)buf * 8192;
                #pragma unroll
                for (int mt = 0; mt < 4; ++mt)
                    #pragma unroll
                    for (int nt = 0; nt < 4; ++nt) {
                        const uint32_t col = (uint32_t)nt * 32 + (uint32_t)t * 8;
                        const uint32_t r0 = (uint32_t)(16 * mt + g) * 128 + col;
                        *(float2*)(smem + bb + SWZ(r0)) = make_float2(s[mt][nt][0], s[mt][nt][1]);
                        *(float2*)(smem + bb + SWZ(r0 + 8 * 128)) = make_float2(s[mt][nt][2], s[mt][nt][3]);
                    }
            }
            named_bar(1 + pair);
            buf ^= 1;
        }
    } else {
        // ================= CONSUMER: softmax + GEMM2, k-slab [64pair, +64) ===
        const int pair = w - 4;
        const uint32_t sS = OFF_S + (uint32_t)pair * 16384;
        float o[4][8][4];
        #pragma unroll
        for (int mt = 0; mt < 4; ++mt)
            #pragma unroll
            for (int nt = 0; nt < 8; ++nt)
                #pragma unroll
                for (int r = 0; r < 4; ++r) o[mt][nt][r] = 0.f;
        float lsum = 0.f, mrun = -1e30f;
        int buf = 0;

        #pragma unroll 1
        for (int ch = 0; ch < 8; ++ch) {
            const int p = ch >> 1, hh2 = ch & 1;
            named_bar(1 + pair);                   // producer's chunk ready

            // load S frag pairs [mt][jt][a0..a3] as float2 (cols 2t,2t+1 / +8)
            float2 sv[4][2][4];
            {
                const uint32_t bb = sS + (uint32_t)buf * 8192;
                #pragma unroll
                for (int mt = 0; mt < 4; ++mt)
                    #pragma unroll
                    for (int jt = 0; jt < 2; ++jt) {
                        const uint32_t c0 = (uint32_t)(16 * jt + 2 * t) * 4;
                        const uint32_t r0 = (uint32_t)(16 * mt + g) * 128;
                        sv[mt][jt][0] = *(const float2*)(smem + bb + SWZ(r0 + c0));
                        sv[mt][jt][1] = *(const float2*)(smem + bb + SWZ(r0 + 8 * 128 + c0));
                        sv[mt][jt][2] = *(const float2*)(smem + bb + SWZ(r0 + c0 + 32));
                        sv[mt][jt][3] = *(const float2*)(smem + bb + SWZ(r0 + 8 * 128 + c0 + 32));
                    }
            }
            buf ^= 1;

            // chunk max -> online update
            {
                float pm = sv[0][0][0].x;
                #pragma unroll
                for (int mt = 0; mt < 4; ++mt)
                    #pragma unroll
                    for (int jt = 0; jt < 2; ++jt)
                        #pragma unroll
                        for (int i = 0; i < 4; ++i)
                            pm = fmaxf(pm, fmaxf(sv[mt][jt][i].x, sv[mt][jt][i].y));
                #pragma unroll
                for (int m = 16; m; m >>= 1)
                    pm = fmaxf(pm, __shfl_xor_sync(0xffffffffu, pm, m));
                if (pm > mrun) {
                    const float rsc = ex2f(mrun - pm);
                    lsum *= rsc;
                    #pragma unroll
                    for (int mt = 0; mt < 4; ++mt)
                        #pragma unroll
                        for (int nt = 0; nt < 8; ++nt)
                            #pragma unroll
                            for (int r = 0; r < 4; ++r) o[mt][nt][r] *= rsc;
                    mrun = pm;
                }
            }

            // exp2 -> fp16 A-frags
            uint32_t pa[4][2][4];
            #pragma unroll
            for (int mt = 0; mt < 4; ++mt)
                #pragma unroll
                for (int jt = 0; jt < 2; ++jt)
                    #pragma unroll
                    for (int i = 0; i < 4; ++i) {
                        const float2 v = sv[mt][jt][i];
                        const float p0 = ex2f(v.x - mrun);
                        const float p1 = ex2f(v.y - mrun);
                        lsum += p0 + p1;
                        pa[mt][jt][i] = packh2_sat(p0, p1);
                    }

            // GEMM2: o += P^T-frag x V1
            #pragma unroll
            for (int jt = 0; jt < 2; ++jt)
                #pragma unroll
                for (int ntp = 0; ntp < 4; ++ntp) {
                    uint32_t vH[4];
                    const uint32_t rb = (uint32_t)(64 * p + 32 * hh2 + 16 * jt + lmA_r) * 128
                                      + (uint32_t)ntp * 32 + lmA_c;
                    ldsm_x4_t(vH, sb + OFF_V1H + SWZ(rb));
                    #pragma unroll
                    for (int h = 0; h < 2; ++h)
                        #pragma unroll
                        for (int mt = 0; mt < 4; ++mt)
                            mma_hf(o[mt][2*ntp+h], pa[mt][jt], vH[2*h], vH[2*h+1]);
                }
        }

        // ---- consumer epilogue: V2 mult + g-reduce -> pair partials ----
        {
            const int k0 = 64 * pair + g;
            #pragma unroll
            for (int nt = 0; nt < 8; ++nt) {
                const int d0 = 8 * nt + 2 * t;
                float r0 = 0.f, r1 = 0.f;
                #pragma unroll
                for (int mt = 0; mt < 4; ++mt) {
                    const float2 vA = *(const float2*)(V2g + (size_t)(k0 + 16 * mt)     * DD + d0);
                    const float2 vB = *(const float2*)(V2g + (size_t)(k0 + 16 * mt + 8) * DD + d0);
                    r0 += o[mt][nt][0] * vA.x + o[mt][nt][2] * vB.x;
                    r1 += o[mt][nt][1] * vA.y + o[mt][nt][3] * vB.y;
                }
                #pragma unroll
                for (int m = 4; m <= 16; m <<= 1) {
                    r0 += __shfl_xor_sync(0xffffffffu, r0, m);
                    r1 += __shfl_xor_sync(0xffffffffu, r1, m);
                }
                if (g == 0) *(float2*)(sRed + pair * 64 + d0) = make_float2(r0, r1);
            }
            #pragma unroll
            for (int m = 16; m; m >>= 1)
                lsum += __shfl_xor_sync(0xffffffffu, lsum, m);
            if (lid == 0) { sLp[pair] = lsum; sM[pair] = mrun; }
        }
    }
    __syncthreads();

    if (tid < 64) {
        float M = sM[0];
        #pragma unroll
        for (int ww = 1; ww < 4; ++ww) M = fmaxf(M, sM[ww]);
        float ssum = 0.f, l = 0.f;
        #pragma unroll
        for (int ww = 0; ww < 4; ++ww) {
            const float sc = ex2f(sM[ww] - M);
            ssum += sc * sRed[ww * 64 + tid];
            l    += sc * sLp[ww];
        }
        out[base + (size_t)qi * DD + tid] = ssum / l;
    }
}

extern "C" void kernel_launch(void* const* d_in, const int* in_sizes, int n_in,
                              void* d_out, int out_size)
{
    const float* q  = (const float*)d_in[0];
    const float* k1 = (const float*)d_in[1];
    const float* v1 = (const float*)d_in[2];
    const float* k2 = (const float*)d_in[3];
    const float* v2 = (const float*)d_in[4];
    float* out = (float*)d_out;

    (void)cudaFuncSetAttribute(trisimp_ws_kernel,
                               cudaFuncAttributeMaxDynamicSharedMemorySize, SMEM_BYTES);
    trisimp_ws_kernel<<<2 * 8 * NQ, 256, SMEM_BYTES>>>(q, k1, v1, k2, v2, out);
}

// round 17
// speedup vs baseline: 1.1860x; 1.1860x over previous
#include <cuda_runtime.h>
#include <cuda_bf16.h>
#include <cuda_fp16.h>
#include <cstdint>

// Fixed shapes: B=2, H=8, N=256, D=64.  One CTA (256 thr, 8 warps) per query.
// R13 base (barrier-free mainloop, q folded into K2, bf16 3-product GEMM1,
// fp16 1-product GEMM2, per-warp online max).  NEW: K1 (bf16 hi/lo) and V1
// (fp16) are converted ONCE per (b,h) by a precompute kernel into swizzled
// global images; the main kernel cp.asyncs them instead of re-converting.
#define NQ 256
#define DD 64
#define NPANEL 4

#define SWZ(x) ((x) ^ (((x) >> 3) & 0x70))

static constexpr uint32_t OFF_K2QH = 0;        // [256 k][64 d] bf16 hi (32 KB)
static constexpr uint32_t OFF_K2QL = 32768;    // lo
static constexpr uint32_t OFF_K1H  = 65536;    // [256 j][64 d] bf16 hi (32 KB)
static constexpr uint32_t OFF_K1L  = 98304;    // lo
static constexpr uint32_t OFF_V1H  = 131072;   // [256 j][64 d] fp16 (32 KB)
static constexpr uint32_t OFF_SRED = 163840;   // [8 warps][64 d] fp32 (2 KB)
static constexpr uint32_t OFF_SLP  = 165888;   // [8] fp32 lsum
static constexpr uint32_t OFF_SM   = 165920;   // [8] fp32 per-warp max
static constexpr uint32_t SMEM_BYTES = 165952;

// Preconverted swizzled images, one 32 KB block per (b,h).
__device__ __align__(16) char g_k1h[16 * 32768];
__device__ __align__(16) char g_k1l[16 * 32768];
__device__ __align__(16) char g_v1h[16 * 32768];

// ---------------- PTX helpers ----------------------------------------------
__device__ __forceinline__ uint32_t smem_u32(const void* p) {
    uint32_t a;
    asm("{ .reg .u64 t; cvta.to.shared.u64 t, %1; cvt.u32.u64 %0, t; }" : "=r"(a) : "l"(p));
    return a;
}
__device__ __forceinline__ float ex2f(float x) {
    float y; asm("ex2.approx.ftz.f32 %0, %1;" : "=f"(y) : "f"(x)); return y;
}
__device__ __forceinline__ void cp16(uint32_t dst, const void* src) {
    asm volatile("cp.async.cg.shared.global [%0], [%1], 16;" :: "r"(dst), "l"(src));
}
__device__ __forceinline__ void cp_commit() { asm volatile("cp.async.commit_group;"); }
__device__ __forceinline__ void cp_wait0()  { asm volatile("cp.async.wait_group 0;" ::: "memory"); }
__device__ __forceinline__ void ldsm_x4(uint32_t* r, uint32_t addr) {
    asm volatile("ldmatrix.sync.aligned.m8n8.x4.shared.b16 {%0,%1,%2,%3}, [%4];"
                 : "=r"(r[0]), "=r"(r[1]), "=r"(r[2]), "=r"(r[3]) : "r"(addr));
}
__device__ __forceinline__ void ldsm_x4_t(uint32_t* r, uint32_t addr) {
    asm volatile("ldmatrix.sync.aligned.m8n8.x4.trans.shared.b16 {%0,%1,%2,%3}, [%4];"
                 : "=r"(r[0]), "=r"(r[1]), "=r"(r[2]), "=r"(r[3]) : "r"(addr));
}
// NOT volatile: pure register ops, scheduler may software-pipeline.
__device__ __forceinline__ void mma_bf(float* c, const uint32_t* a, uint32_t b0, uint32_t b1) {
    asm("mma.sync.aligned.m16n8k16.row.col.f32.bf16.bf16.f32 "
        "{%0,%1,%2,%3}, {%4,%5,%6,%7}, {%8,%9}, {%0,%1,%2,%3};"
        : "+f"(c[0]), "+f"(c[1]), "+f"(c[2]), "+f"(c[3])
        : "r"(a[0]), "r"(a[1]), "r"(a[2]), "r"(a[3]), "r"(b0), "r"(b1));
}
__device__ __forceinline__ void mma_hf(float* c, const uint32_t* a, uint32_t b0, uint32_t b1) {
    asm("mma.sync.aligned.m16n8k16.row.col.f32.f16.f16.f32 "
        "{%0,%1,%2,%3}, {%4,%5,%6,%7}, {%8,%9}, {%0,%1,%2,%3};"
        : "+f"(c[0]), "+f"(c[1]), "+f"(c[2]), "+f"(c[3])
        : "r"(a[0]), "r"(a[1]), "r"(a[2]), "r"(a[3]), "r"(b0), "r"(b1));
}
__device__ __forceinline__ void split2(float x, float y, uint32_t& h, uint32_t& l) {
    __nv_bfloat162 h2 = __floats2bfloat162_rn(x, y);
    __nv_bfloat162 l2 = __floats2bfloat162_rn(x - __low2float(h2), y - __high2float(h2));
    h = *(uint32_t*)&h2; l = *(uint32_t*)&l2;
}
__device__ __forceinline__ uint32_t packh2_sat(float x, float y) {   // x -> low half
    uint32_t r;
    asm("cvt.rn.satfinite.f16x2.f32 %0, %1, %2;" : "=r"(r) : "f"(y), "f"(x));
    return r;
}

// ---------------- Precompute kernel: convert K1/V1 once per head ------------
__global__ __launch_bounds__(256, 4)
void precvt_kernel(const float* __restrict__ k1, const float* __restrict__ v1)
{
    const int bh = blockIdx.x >> 2, qr = blockIdx.x & 3;   // quarter of rows
    const int tid = threadIdx.x, dp = tid & 31;
    const float2* K1g2 = (const float2*)(k1 + (size_t)bh * NQ * DD) + qr * 2048;
    const float2* V1g2 = (const float2*)(v1 + (size_t)bh * NQ * DD) + qr * 2048;
    char* dK1h = g_k1h + (size_t)bh * 32768;
    char* dK1l = g_k1l + (size_t)bh * 32768;
    char* dV1  = g_v1h + (size_t)bh * 32768;

    for (int e2 = tid; e2 < 2048; e2 += 256) {
        const int r = qr * 64 + (e2 >> 5);
        const uint32_t off = SWZ((uint32_t)r * 128 + (uint32_t)dp * 4);
        {
            const float2 x = K1g2[e2];
            uint32_t h, l; split2(x.x, x.y, h, l);
            *(uint32_t*)(dK1h + off) = h;
            *(uint32_t*)(dK1l + off) = l;
        }
        {
            const float2 x = V1g2[e2];
            const __half2 hh = __floats2half2_rn(x.x, x.y);
            *(uint32_t*)(dV1 + off) = *(const uint32_t*)&hh;
        }
    }
}

// ---------------- Main kernel ----------------------------------------------
__global__ __launch_bounds__(256, 1)
void trisimp_mma9_kernel(const float* __restrict__ q,  const float* __restrict__ k2,
                         const float* __restrict__ v2, float* __restrict__ out)
{
    extern __shared__ char smem[];
    const uint32_t sb = smem_u32(smem);
    const int tid = threadIdx.x, w = tid >> 5, lid = tid & 31;
    const int g = lid >> 2, t = lid & 3;

    const int bhq = blockIdx.x, qi = bhq & 255, bh = bhq >> 8;
    const size_t base = (size_t)bh * NQ * DD;
    const float* Qrow = q  + base + (size_t)qi * DD;
    const float* K2g  = k2 + base;
    const float* V2g  = v2 + base;

    // ---- cp.async the preconverted K1 hi/lo + V1 images (96 KB total) ----
    {
        const char* sK1h = g_k1h + (size_t)bh * 32768;
        const char* sK1l = g_k1l + (size_t)bh * 32768;
        const char* sV1  = g_v1h + (size_t)bh * 32768;
        for (int i = tid; i < 2048; i += 256) {
            const uint32_t o16 = (uint32_t)i * 16;
            cp16(sb + OFF_K1H + o16, sK1h + o16);
            cp16(sb + OFF_K1L + o16, sK1l + o16);
            cp16(sb + OFF_V1H + o16, sV1  + o16);
        }
        cp_commit();
    }

    const int dp = tid & 31;
    const float2 qme = ((const float2*)Qrow)[dp];
    const float qx = qme.x * 1.4426950408889634f;
    const float qy = qme.y * 1.4426950408889634f;

    // ---- convert K2q = q*K2*log2e (bf16 hi/lo) -- overlaps cp.async flight ----
    {
        const float2* K2g2 = (const float2*)K2g;
        for (int e2 = tid; e2 < NQ * 32; e2 += 256) {
            const int r = e2 >> 5;
            const float2 x = K2g2[e2];
            uint32_t h, l; split2(qx * x.x, qy * x.y, h, l);
            const uint32_t off = SWZ((uint32_t)r * 128 + (uint32_t)dp * 4);
            *(uint32_t*)(smem + OFF_K2QH + off) = h;
            *(uint32_t*)(smem + OFF_K2QL + off) = l;
        }
    }
    cp_wait0();
    __syncthreads();                             // the ONLY mainloop barrier

    const uint32_t lmA_r = (uint32_t)(lid & 15), lmA_c = (uint32_t)(lid >> 4) * 16;
    const uint32_t lmB_r = (uint32_t)((lid >> 4) * 8 + (lid & 7)), lmB_c = (uint32_t)((lid >> 3) & 1) * 16;

    float o[2][8][4];
    #pragma unroll
    for (int mt = 0; mt < 2; ++mt)
        #pragma unroll
        for (int nt = 0; nt < 8; ++nt)
            #pragma unroll
            for (int r = 0; r < 4; ++r) o[mt][nt][r] = 0.f;
    float lsum = 0.f;
    float mrun = -1e30f;                         // running per-warp max (log2 units)

    #pragma unroll 1
    for (int p = 0; p < NPANEL; ++p) {
        // ---- GEMM1: S[k32(w), j64(p)] = sum_d K2q[k,d]*K1[j,d] (bf16, 3 products) ----
        float s[2][8][4];
        #pragma unroll
        for (int mt = 0; mt < 2; ++mt)
            #pragma unroll
            for (int nt = 0; nt < 8; ++nt)
                #pragma unroll
                for (int r = 0; r < 4; ++r) s[mt][nt][r] = 0.f;

        #pragma unroll
        for (int kc = 0; kc < 4; ++kc) {
            uint32_t aH[2][4], aL[2][4];
            #pragma unroll
            for (int mt = 0; mt < 2; ++mt) {
                const uint32_t rb = (uint32_t)(32 * w + 16 * mt + lmA_r) * 128
                                  + (uint32_t)kc * 32 + lmA_c;
                ldsm_x4(aH[mt], sb + OFF_K2QH + SWZ(rb));
                ldsm_x4(aL[mt], sb + OFF_K2QL + SWZ(rb));
            }
            #pragma unroll
            for (int cp = 0; cp < 4; ++cp) {
                uint32_t bH[4], bL[4];
                const uint32_t rb = (uint32_t)(64 * p + 16 * cp + lmB_r) * 128
                                  + (uint32_t)kc * 32 + lmB_c;
                ldsm_x4(bH, sb + OFF_K1H + SWZ(rb));
                ldsm_x4(bL, sb + OFF_K1L + SWZ(rb));
                #pragma unroll
                for (int h = 0; h < 2; ++h)
                    #pragma unroll
                    for (int mt = 0; mt < 2; ++mt)
                        mma_bf(s[mt][2*cp+h], aH[mt], bH[2*h], bH[2*h+1]);
                #pragma unroll
                for (int h = 0; h < 2; ++h)
                    #pragma unroll
                    for (int mt = 0; mt < 2; ++mt)
                        mma_bf(s[mt][2*cp+h], aH[mt], bL[2*h], bL[2*h+1]);
                #pragma unroll
                for (int h = 0; h < 2; ++h)
                    #pragma unroll
                    for (int mt = 0; mt < 2; ++mt)
                        mma_bf(s[mt][2*cp+h], aL[mt], bH[2*h], bH[2*h+1]);
            }
        }

        // ---- online max update (warp-local, order-invariant) ----
        {
            float pm = s[0][0][0];
            #pragma unroll
            for (int mt = 0; mt < 2; ++mt)
                #pragma unroll
                for (int nt = 0; nt < 8; ++nt)
                    #pragma unroll
                    for (int r = 0; r < 4; ++r) pm = fmaxf(pm, s[mt][nt][r]);
            #pragma unroll
            for (int m = 16; m; m >>= 1)
                pm = fmaxf(pm, __shfl_xor_sync(0xffffffffu, pm, m));
            if (pm > mrun) {                     // warp-uniform branch
                const float rsc = ex2f(mrun - pm);
                lsum *= rsc;
                #pragma unroll
                for (int mt = 0; mt < 2; ++mt)
                    #pragma unroll
                    for (int nt = 0; nt < 8; ++nt)
                        #pragma unroll
                        for (int r = 0; r < 4; ++r) o[mt][nt][r] *= rsc;
                mrun = pm;
            }
        }

        // ---- exp2(s - m) -> fp16 P, GEMM2 fp16 1-product ----
        #pragma unroll
        for (int c = 0; c < 4; ++c) {
            uint32_t paH[2][4];
            #pragma unroll
            for (int mt = 0; mt < 2; ++mt) {
                #pragma unroll
                for (int h = 0; h < 2; ++h) {
                    float* cc = s[mt][2 * c + h];
                    const float p0 = ex2f(cc[0] - mrun);
                    const float p1 = ex2f(cc[1] - mrun);
                    const float p2 = ex2f(cc[2] - mrun);
                    const float p3 = ex2f(cc[3] - mrun);
                    lsum += (p0 + p1) + (p2 + p3);
                    paH[mt][2*h]   = packh2_sat(p0, p1);   // rows g
                    paH[mt][2*h+1] = packh2_sat(p2, p3);   // rows g+8
                }
            }
            #pragma unroll
            for (int ntp = 0; ntp < 4; ++ntp) {
                uint32_t vH[4];
                const uint32_t rb = (uint32_t)(64 * p + 16 * c + lmA_r) * 128
                                  + (uint32_t)ntp * 32 + lmA_c;
                ldsm_x4_t(vH, sb + OFF_V1H + SWZ(rb));
                #pragma unroll
                for (int h = 0; h < 2; ++h)
                    #pragma unroll
                    for (int mt = 0; mt < 2; ++mt)
                        mma_hf(o[mt][2*ntp+h], paH[mt], vH[2*h], vH[2*h+1]);
            }
        }
    }

    // ---- epilogue: combine warps with per-warp max rescale ----
    float* sRed = (float*)(smem + OFF_SRED);
    float* sLp  = (float*)(smem + OFF_SLP);
    float* sM   = (float*)(smem + OFF_SM);
    {
        const int k0 = 32 * w + g;
        #pragma unroll
        for (int nt = 0; nt < 8; ++nt) {
            const int d0 = 8 * nt + 2 * t;
            const float2 vA = *(const float2*)(V2g + (size_t)(k0)      * DD + d0);
            const float2 vB = *(const float2*)(V2g + (size_t)(k0 + 8)  * DD + d0);
            const float2 vC = *(const float2*)(V2g + (size_t)(k0 + 16) * DD + d0);
            const float2 vD = *(const float2*)(V2g + (size_t)(k0 + 24) * DD + d0);
            float r0 = o[0][nt][0]*vA.x + o[0][nt][2]*vB.x + o[1][nt][0]*vC.x + o[1][nt][2]*vD.x;
            float r1 = o[0][nt][1]*vA.y + o[0][nt][3]*vB.y + o[1][nt][1]*vC.y + o[1][nt][3]*vD.y;
            #pragma unroll
            for (int m = 4; m <= 16; m <<= 1) {
                r0 += __shfl_xor_sync(0xffffffffu, r0, m);
                r1 += __shfl_xor_sync(0xffffffffu, r1, m);
            }
            if (g == 0) *(float2*)(sRed + w * 64 + d0) = make_float2(r0, r1);
        }
        #pragma unroll
        for (int m = 16; m; m >>= 1)
            lsum += __shfl_xor_sync(0xffffffffu, lsum, m);
        if (lid == 0) { sLp[w] = lsum; sM[w] = mrun; }
    }
    __syncthreads();

    if (tid < 64) {
        float M = sM[0];
        #pragma unroll
        for (int ww = 1; ww < 8; ++ww) M = fmaxf(M, sM[ww]);
        float ssum = 0.f, l = 0.f;
        #pragma unroll
        for (int ww = 0; ww < 8; ++ww) {
            const float sc = ex2f(sM[ww] - M);
            ssum += sc * sRed[ww * 64 + tid];
            l    += sc * sLp[ww];
        }
        out[base + (size_t)qi * DD + tid] = ssum / l;
    }
}

extern "C" void kernel_launch(void* const* d_in, const int* in_sizes, int n_in,
                              void* d_out, int out_size)
{
    const float* q  = (const float*)d_in[0];
    const float* k1 = (const float*)d_in[1];
    const float* v1 = (const float*)d_in[2];
    const float* k2 = (const float*)d_in[3];
    const float* v2 = (const float*)d_in[4];
    float* out = (float*)d_out;

    precvt_kernel<<<64, 256>>>(k1, v1);
    (void)cudaFuncSetAttribute(trisimp_mma9_kernel,
                               cudaFuncAttributeMaxDynamicSharedMemorySize, SMEM_BYTES);
    trisimp_mma9_kernel<<<2 * 8 * NQ, 256, SMEM_BYTES>>>(q, k2, v2, out);
}